// round 4
// baseline (speedup 1.0000x reference)
#include <cuda_runtime.h>
#include <cuda_bf16.h>
#include <math.h>

#define BB 4
#define NN 512
#define INF_D 1e18

// ---------------------------------------------------------------------------
// XLA:CPU inline expf (Cephes/Eigen style, llvm_ir_runtime GenerateVF32Exp),
// with aarch64 FMA contraction of the MulAdd chains.
// ---------------------------------------------------------------------------
__device__ __forceinline__ float xla_expf(float xin)
{
    float x = fminf(xin,  88.3762626647950f);
    x       = fmaxf(x,   -88.3762626647949f);
    float fx = floorf(fmaf(x, 1.44269504088896341f, 0.5f));
    float t1 = __fmul_rn(fx, 0.693359375f);      // Cody-Waite hi
    float t2 = __fmul_rn(fx, -2.12194440e-4f);   // Cody-Waite lo
    float xr = __fsub_rn(x, t1);
    xr       = __fsub_rn(xr, t2);
    float zz = __fmul_rn(xr, xr);
    float y  = fmaf(1.9875691500E-4f, xr, 1.3981999507E-3f);
    y = fmaf(y, xr, 8.3334519073E-3f);
    y = fmaf(y, xr, 4.1665795894E-2f);
    y = fmaf(y, xr, 1.6666665459E-1f);
    y = fmaf(y, xr, 5.0000001201E-1f);
    y = fmaf(y, zz, xr);
    y = __fadd_rn(y, 1.0f);
    int n = (int)fx;
    float p2n = __int_as_float((n + 127) << 23);
    return fmaxf(__fmul_rn(y, p2n), xin);        // max with ORIGINAL input
}

// ---------------------------------------------------------------------------
// XLA:CPU inline logf (Cephes, GenerateVF32Log), fused Horner.
// Valid path for inputs in (0, inf) normal range (ours: [~0.01, 1+1e-8]).
// ---------------------------------------------------------------------------
__device__ __forceinline__ float xla_logf(float xin)
{
    float x = fmaxf(xin, 1.17549435e-38f);       // min_norm_pos
    int ix   = __float_as_int(x);
    int emm0 = (int)((unsigned int)ix >> 23) - 0x7e;
    float e  = (float)emm0;
    x = __int_as_float((ix & ~0x7f800000) | 0x3f000000);   // mantissa in [0.5,1)
    bool m = x < 0.707106781186547524f;
    float tmp = m ? x : 0.0f;
    x = __fsub_rn(x, 1.0f);
    e = __fsub_rn(e, m ? 1.0f : 0.0f);
    x = __fadd_rn(x, tmp);
    float z = __fmul_rn(x, x);
    float y = fmaf(7.0376836292E-2f, x, -1.1514610310E-1f);
    y = fmaf(y, x,  1.1676998740E-1f);
    y = fmaf(y, x, -1.2420140846E-1f);
    y = fmaf(y, x,  1.4249322787E-1f);
    y = fmaf(y, x, -1.6668057665E-1f);
    y = fmaf(y, x,  2.0000714765E-1f);
    y = fmaf(y, x, -2.4999993993E-1f);
    y = fmaf(y, x,  3.3333331174E-1f);
    y = __fmul_rn(y, x);
    y = __fmul_rn(y, z);
    y = fmaf(e, -2.12194440e-4f, y);             // + e*q1
    y = fmaf(z, -0.5f, y);                       // - 0.5*z (contracted)
    x = __fadd_rn(x, y);
    x = fmaf(e, 0.693359375f, x);                // + e*q2
    return x;
}

// ---------------------------------------------------------------------------
// Focal class cost — eager-jax op-by-op: every basic op standalone rn, no
// cross-op contraction. pow(p,2) -> p*p (algebraic simplifier).
// ---------------------------------------------------------------------------
__device__ __forceinline__ float cost_class_f(float x)
{
    float e   = xla_expf(-x);                            // logistic expansion
    float p   = __fdiv_rn(1.0f, __fadd_rn(1.0f, e));
    float omp = __fsub_rn(1.0f, p);
    float lo  = xla_logf(__fadd_rn(omp, 1e-8f));
    float lp  = xla_logf(__fadd_rn(p,   1e-8f));
    float pp  = __fmul_rn(p,   p);
    float oo  = __fmul_rn(omp, omp);
    float neg = __fmul_rn(__fmul_rn(0.75f, pp), -lo);
    float pos = __fmul_rn(__fmul_rn(0.25f, oo), -lp);
    return __fsub_rn(pos, neg);
}

__device__ __forceinline__ float cost_entry_f(float cls, float px, float py,
                                              float gx, float gy)
{
    float coord = __fadd_rn(fabsf(__fsub_rn(px, gx)), fabsf(__fsub_rn(py, gy)));
    return __fadd_rn(cls, coord);
}

// ---------------------------------------------------------------------------
// Kernel 1: C matrix + pred_idx outputs. grid=(NN,BB), block=NN.
// ---------------------------------------------------------------------------
__global__ void cost_kernel(const float* __restrict__ logits,
                            const float2* __restrict__ pred_pts,
                            const float2* __restrict__ gt_pts,
                            float* __restrict__ pred_out,
                            float* __restrict__ Cf)
{
    const int i = blockIdx.x;
    const int b = blockIdx.y;
    const int j = threadIdx.x;

    __shared__ float s_cls, s_px, s_py;
    if (j == 0) {
        s_cls = cost_class_f(logits[b * NN + i]);
        float2 pp = pred_pts[b * NN + i];
        s_px = pp.x; s_py = pp.y;
        pred_out[b * NN + i] = (float)i;
    }
    __syncthreads();

    float2 gp = gt_pts[b * NN + j];
    Cf[((size_t)b * NN + i) * NN + j] = cost_entry_f(s_cls, s_px, s_py, gp.x, gp.y);
}

// ---------------------------------------------------------------------------
// Kernel 2: replica of the reference's (buggy) LSA — minv/way never persist
// (numpy .copy() bug): each step is a fresh argmin of
// (f64)C[i0-1][j] - u[i0] - v[j] over unused j; augment = p[j_final] = i.
// One block per batch; thread t owns column t+1; v[col] in a register.
// ---------------------------------------------------------------------------
__global__ void __launch_bounds__(NN, 1)
lsa_kernel(const float* __restrict__ logits,
           const float2* __restrict__ pred_pts,
           const float2* __restrict__ gt_pts,
           float* __restrict__ gt_out)
{
    const int b   = blockIdx.x;
    const int t   = threadIdx.x;
    const int col = t + 1;                    // 1..NN

    __shared__ float  s_cls[NN], s_px[NN], s_py[NN];
    __shared__ double u[NN + 1];
    __shared__ int    p[NN + 1];
    __shared__ double red_val[16];
    __shared__ int    red_idx[16];

    {
        s_cls[t] = cost_class_f(logits[b * NN + t]);
        float2 pp = pred_pts[b * NN + t];
        s_px[t] = pp.x; s_py[t] = pp.y;
    }
    const float2 g  = gt_pts[b * NN + t];
    const float  gx = g.x, gy = g.y;

    u[col] = 0.0; p[col] = 0;
    if (t == 0) { u[0] = 0.0; p[0] = 0; }
    double myV = 0.0;                          // v[col], owner-private
    __syncthreads();

    const int lane = t & 31;

    for (int i = 1; i <= NN; ++i) {
        bool myUsed = false;
        int  j0     = 0;
        if (t == 0) p[0] = i;
        __syncthreads();

        while (true) {
            if (col == j0) myUsed = true;      // used[j0]=True at loop top
            const int    i0  = p[j0];
            const double ui0 = u[i0];

            double cand;
            if (myUsed) {
                cand = INF_D;
            } else {
                float cf = cost_entry_f(s_cls[i0 - 1], s_px[i0 - 1], s_py[i0 - 1],
                                        gx, gy);      // == C[i0-1][col-1] bitwise
                cand = ((double)cf - ui0) - myV;      // (c - u[i0]) - v[j]
            }

            // block argmin: min value, lowest index on ties (np.argmin)
            double bv = cand; int bi = col;
            #pragma unroll
            for (int off = 16; off; off >>= 1) {
                double ov = __shfl_down_sync(0xffffffffu, bv, off);
                int    oi = __shfl_down_sync(0xffffffffu, bi, off);
                if (ov < bv || (ov == bv && oi < bi)) { bv = ov; bi = oi; }
            }
            if (lane == 0) { red_val[t >> 5] = bv; red_idx[t >> 5] = bi; }
            __syncthreads();
            bv = (lane < 16) ? red_val[lane] : INF_D;
            bi = (lane < 16) ? red_idx[lane] : 0x7fffffff;
            #pragma unroll
            for (int off = 8; off; off >>= 1) {
                double ov = __shfl_down_sync(0xffffffffu, bv, off);
                int    oi = __shfl_down_sync(0xffffffffu, bi, off);
                if (ov < bv || (ov == bv && oi < bi)) { bv = ov; bi = oi; }
            }
            const double delta = __shfl_sync(0xffffffffu, bv, 0);
            const int    j1    = __shfl_sync(0xffffffffu, bi, 0);

            if (myUsed) { u[p[col]] += delta; myV -= delta; }
            if (t == 0)   u[i] += delta;       // index 0: p[0]=i

            j0 = j1;
            __syncthreads();
            if (p[j0] == 0) break;
        }

        if (t == 0) p[j0] = i;                 // way[] all zero -> single write
    }
    __syncthreads();

    gt_out[(size_t)b * NN + (p[col] - 1)] = (float)(col - 1);
}

// ---------------------------------------------------------------------------
// out = [pred_idx (B*N) | gt_idx (B*N) | C (B*N*N)], float32
// ---------------------------------------------------------------------------
extern "C" void kernel_launch(void* const* d_in, const int* in_sizes, int n_in,
                              void* d_out, int out_size)
{
    const float*  logits   = (const float*) d_in[0];
    const float2* pred_pts = (const float2*)d_in[1];
    const float2* gt_pts   = (const float2*)d_in[2];
    // d_in[3] = gt_mask (all true, unused)

    float* out  = (float*)d_out;
    float* pred = out;
    float* gt   = out + BB * NN;
    float* Cf   = out + 2 * BB * NN;

    dim3 cgrid(NN, BB);
    cost_kernel<<<cgrid, NN>>>(logits, pred_pts, gt_pts, pred, Cf);
    lsa_kernel<<<BB, NN>>>(logits, pred_pts, gt_pts, gt);
}

// round 5
// speedup vs baseline: 3.3216x; 3.3216x over previous
#include <cuda_runtime.h>
#include <cuda_bf16.h>
#include <math.h>

#define BB 4
#define NN 512
#define SIGN64 0x8000000000000000ull

// ---------------------------------------------------------------------------
// XLA:CPU inline expf (Cephes, llvm_ir_runtime GenerateVF32Exp), aarch64 FMA.
// DO NOT TOUCH — bit-exactness verified (R4 pass, rel_err 1e-8).
// ---------------------------------------------------------------------------
__device__ __forceinline__ float xla_expf(float xin)
{
    float x = fminf(xin,  88.3762626647950f);
    x       = fmaxf(x,   -88.3762626647949f);
    float fx = floorf(fmaf(x, 1.44269504088896341f, 0.5f));
    float t1 = __fmul_rn(fx, 0.693359375f);
    float t2 = __fmul_rn(fx, -2.12194440e-4f);
    float xr = __fsub_rn(x, t1);
    xr       = __fsub_rn(xr, t2);
    float zz = __fmul_rn(xr, xr);
    float y  = fmaf(1.9875691500E-4f, xr, 1.3981999507E-3f);
    y = fmaf(y, xr, 8.3334519073E-3f);
    y = fmaf(y, xr, 4.1665795894E-2f);
    y = fmaf(y, xr, 1.6666665459E-1f);
    y = fmaf(y, xr, 5.0000001201E-1f);
    y = fmaf(y, zz, xr);
    y = __fadd_rn(y, 1.0f);
    int n = (int)fx;
    float p2n = __int_as_float((n + 127) << 23);
    return fmaxf(__fmul_rn(y, p2n), xin);
}

// XLA:CPU inline logf (Cephes, GenerateVF32Log). DO NOT TOUCH.
__device__ __forceinline__ float xla_logf(float xin)
{
    float x = fmaxf(xin, 1.17549435e-38f);
    int ix   = __float_as_int(x);
    int emm0 = (int)((unsigned int)ix >> 23) - 0x7e;
    float e  = (float)emm0;
    x = __int_as_float((ix & ~0x7f800000) | 0x3f000000);
    bool m = x < 0.707106781186547524f;
    float tmp = m ? x : 0.0f;
    x = __fsub_rn(x, 1.0f);
    e = __fsub_rn(e, m ? 1.0f : 0.0f);
    x = __fadd_rn(x, tmp);
    float z = __fmul_rn(x, x);
    float y = fmaf(7.0376836292E-2f, x, -1.1514610310E-1f);
    y = fmaf(y, x,  1.1676998740E-1f);
    y = fmaf(y, x, -1.2420140846E-1f);
    y = fmaf(y, x,  1.4249322787E-1f);
    y = fmaf(y, x, -1.6668057665E-1f);
    y = fmaf(y, x,  2.0000714765E-1f);
    y = fmaf(y, x, -2.4999993993E-1f);
    y = fmaf(y, x,  3.3333331174E-1f);
    y = __fmul_rn(y, x);
    y = __fmul_rn(y, z);
    y = fmaf(e, -2.12194440e-4f, y);
    y = fmaf(z, -0.5f, y);
    x = __fadd_rn(x, y);
    x = fmaf(e, 0.693359375f, x);
    return x;
}

__device__ __forceinline__ float cost_class_f(float x)
{
    float e   = xla_expf(-x);
    float p   = __fdiv_rn(1.0f, __fadd_rn(1.0f, e));
    float omp = __fsub_rn(1.0f, p);
    float lo  = xla_logf(__fadd_rn(omp, 1e-8f));
    float lp  = xla_logf(__fadd_rn(p,   1e-8f));
    float pp  = __fmul_rn(p,   p);
    float oo  = __fmul_rn(omp, omp);
    float neg = __fmul_rn(__fmul_rn(0.75f, pp), -lo);
    float pos = __fmul_rn(__fmul_rn(0.25f, oo), -lp);
    return __fsub_rn(pos, neg);
}

__device__ __forceinline__ float cost_entry_f(float cls, float px, float py,
                                              float gx, float gy)
{
    float coord = __fadd_rn(fabsf(__fsub_rn(px, gx)), fabsf(__fsub_rn(py, gy)));
    return __fadd_rn(cls, coord);
}

// ---------------------------------------------------------------------------
// Kernel 1: C matrix + pred_idx outputs. grid=(NN,BB), block=NN. (unchanged)
// ---------------------------------------------------------------------------
__global__ void cost_kernel(const float* __restrict__ logits,
                            const float2* __restrict__ pred_pts,
                            const float2* __restrict__ gt_pts,
                            float* __restrict__ pred_out,
                            float* __restrict__ Cf)
{
    const int i = blockIdx.x;
    const int b = blockIdx.y;
    const int j = threadIdx.x;

    __shared__ float s_cls, s_px, s_py;
    if (j == 0) {
        s_cls = cost_class_f(logits[b * NN + i]);
        float2 pp = pred_pts[b * NN + i];
        s_px = pp.x; s_py = pp.y;
        pred_out[b * NN + i] = (float)i;
    }
    __syncthreads();

    float2 gp = gt_pts[b * NN + j];
    Cf[((size_t)b * NN + i) * NN + j] = cost_entry_f(s_cls, s_px, s_py, gp.x, gp.y);
}

// ---------------------------------------------------------------------------
// Kernel 2: reference-buggy LSA, latency-optimized.
// 128 threads / batch; thread t owns cols 4t+1..4t+4 (1-indexed).
// f64 cand values bit-identical to reference; argmin via sortable-u64 keys
// (integer compares), warp min via two __reduce_min_sync passes.
// Walk invariants used for prefetch: p[] and u[p[j1]] static during a walk;
// u[i] == 0 at row start.
// ---------------------------------------------------------------------------
__global__ void __launch_bounds__(128, 1)
lsa_kernel(const float* __restrict__ logits,
           const float2* __restrict__ pred_pts,
           const float2* __restrict__ gt_pts,
           float* __restrict__ gt_out)
{
    const int b    = blockIdx.x;
    const int t    = threadIdx.x;
    const int lane = t & 31;
    const int w    = t >> 5;
    const int c0   = 4 * t + 1;            // first owned column (1-indexed)

    __shared__ float  s_cls[NN], s_px[NN], s_py[NN];
    __shared__ double u[NN + 1];
    __shared__ int    p[NN + 1];
    __shared__ unsigned long long red_key[4];
    __shared__ int    red_col[4];

    for (int r = t; r < NN; r += 128) {
        s_cls[r] = cost_class_f(logits[b * NN + r]);
        float2 pp = pred_pts[b * NN + r];
        s_px[r] = pp.x; s_py[r] = pp.y;
    }
    float gx[4], gy[4];
    #pragma unroll
    for (int k = 0; k < 4; k++) {
        float2 g = gt_pts[b * NN + 4 * t + k];
        gx[k] = g.x; gy[k] = g.y;
    }
    #pragma unroll
    for (int k = 0; k < 4; k++) { u[c0 + k] = 0.0; p[c0 + k] = 0; }
    double v[4] = {0.0, 0.0, 0.0, 0.0};
    __syncthreads();

    for (int i = 1; i <= NN; ++i) {
        unsigned usedMask = 0;
        int j0 = 0;

        // prefetch step-0 state: i0 = i, u[i] == 0 (i never matched/active yet)
        double pre[4];
        {
            const float cls0 = s_cls[i - 1], px0 = s_px[i - 1], py0 = s_py[i - 1];
            #pragma unroll
            for (int k = 0; k < 4; k++) {
                float cf = cost_entry_f(cls0, px0, py0, gx[k], gy[k]);
                pre[k] = (double)cf - 0.0;     // (c - u[i0]), u[i]=0 at row start
            }
        }
        __syncthreads();   // prev row: p[jfinal]=i-1 write + final u updates visible

        for (;;) {
            // mark used[j0] (loop-top semantics of the reference)
            unsigned d = (unsigned)j0 - (unsigned)c0;
            if (d < 4u) usedMask |= 1u << d;

            // cand_k = (c - u[i0]) - v[k]   (exact reference f64 order)
            unsigned long long key[4];
            #pragma unroll
            for (int k = 0; k < 4; k++) {
                double cd = pre[k] - v[k];
                long long bits = __double_as_longlong(cd);
                unsigned long long kk = (bits >= 0)
                    ? ((unsigned long long)bits ^ SIGN64)
                    : ~(unsigned long long)bits;
                key[k] = ((usedMask >> k) & 1u) ? ~0ull : kk;
            }

            // local argmin (lowest col on ties)
            unsigned long long lk = key[0]; int lc = c0;
            #pragma unroll
            for (int k = 1; k < 4; k++)
                if (key[k] < lk) { lk = key[k]; lc = c0 + k; }

            // warp u64 min via two u32 redux passes (exact)
            unsigned hi  = (unsigned)(lk >> 32);
            unsigned mhi = __reduce_min_sync(0xffffffffu, hi);
            unsigned lo2 = (hi == mhi) ? (unsigned)lk : 0xffffffffu;
            unsigned mlo = __reduce_min_sync(0xffffffffu, lo2);
            unsigned long long mk = ((unsigned long long)mhi << 32) | mlo;

            // winning column within warp: lowest lane matching -> lowest col
            unsigned ball = __ballot_sync(0xffffffffu, lk == mk);
            int src  = __ffs(ball) - 1;
            int wcol = __shfl_sync(0xffffffffu, lc, src);
            if (lane == 0) { red_key[w] = mk; red_col[w] = wcol; }
            __syncthreads();   // bar1: partials visible

            // stage 2: 4 partials, serial (lower warp = lower cols on ties)
            unsigned long long bk = red_key[0]; int j1 = red_col[0];
            #pragma unroll
            for (int w2 = 1; w2 < 4; w2++) {
                unsigned long long kk = red_key[w2];
                if (kk < bk) { bk = kk; j1 = red_col[w2]; }
            }
            long long db = (long long)((bk & SIGN64) ? (bk ^ SIGN64) : ~bk);
            const double delta = __longlong_as_double(db);

            // prefetch next step (p[], u[p[j1]], s_* static during the walk)
            const int  i0n = p[j1];
            const bool brk = (i0n == 0);
            if (!brk) {
                const double ui0n = u[i0n];
                const float cls0 = s_cls[i0n - 1], px0 = s_px[i0n - 1], py0 = s_py[i0n - 1];
                #pragma unroll
                for (int k = 0; k < 4; k++) {
                    float cf = cost_entry_f(cls0, px0, py0, gx[k], gy[k]);
                    pre[k] = (double)cf - ui0n;
                }
            }

            // u[p[used]] += delta ; v[used] -= delta ; index 0 -> u[i] += delta
            #pragma unroll
            for (int k = 0; k < 4; k++)
                if ((usedMask >> k) & 1u) { u[p[c0 + k]] += delta; v[k] -= delta; }
            if (t == 0) u[i] += delta;

            j0 = j1;
            if (brk) break;       // visibility handled by next row-top barrier
            __syncthreads();      // bar2: u updates + red_* reuse
        }

        if (t == 0) p[j0] = i;    // way[] all zero in reference -> single write
    }
    __syncthreads();

    #pragma unroll
    for (int k = 0; k < 4; k++)
        gt_out[b * NN + (p[c0 + k] - 1)] = (float)(c0 + k - 1);
}

// ---------------------------------------------------------------------------
// out = [pred_idx (B*N) | gt_idx (B*N) | C (B*N*N)], float32
// ---------------------------------------------------------------------------
extern "C" void kernel_launch(void* const* d_in, const int* in_sizes, int n_in,
                              void* d_out, int out_size)
{
    const float*  logits   = (const float*) d_in[0];
    const float2* pred_pts = (const float2*)d_in[1];
    const float2* gt_pts   = (const float2*)d_in[2];
    // d_in[3] = gt_mask (all true, unused)

    float* out  = (float*)d_out;
    float* pred = out;
    float* gt   = out + BB * NN;
    float* Cf   = out + 2 * BB * NN;

    dim3 cgrid(NN, BB);
    cost_kernel<<<cgrid, NN>>>(logits, pred_pts, gt_pts, pred, Cf);
    lsa_kernel<<<BB, 128>>>(logits, pred_pts, gt_pts, gt);
}

// round 7
// speedup vs baseline: 3.7523x; 1.1297x over previous
#include <cuda_runtime.h>
#include <cuda_bf16.h>
#include <math.h>

#define BB 4
#define NN 512
#define SIGN64 0x8000000000000000ull

// ---------------------------------------------------------------------------
// XLA:CPU inline expf (Cephes, llvm_ir_runtime GenerateVF32Exp), aarch64 FMA.
// DO NOT TOUCH — bit-exactness verified (R4/R5 pass, rel_err 1e-8).
// ---------------------------------------------------------------------------
__device__ __forceinline__ float xla_expf(float xin)
{
    float x = fminf(xin,  88.3762626647950f);
    x       = fmaxf(x,   -88.3762626647949f);
    float fx = floorf(fmaf(x, 1.44269504088896341f, 0.5f));
    float t1 = __fmul_rn(fx, 0.693359375f);
    float t2 = __fmul_rn(fx, -2.12194440e-4f);
    float xr = __fsub_rn(x, t1);
    xr       = __fsub_rn(xr, t2);
    float zz = __fmul_rn(xr, xr);
    float y  = fmaf(1.9875691500E-4f, xr, 1.3981999507E-3f);
    y = fmaf(y, xr, 8.3334519073E-3f);
    y = fmaf(y, xr, 4.1665795894E-2f);
    y = fmaf(y, xr, 1.6666665459E-1f);
    y = fmaf(y, xr, 5.0000001201E-1f);
    y = fmaf(y, zz, xr);
    y = __fadd_rn(y, 1.0f);
    int n = (int)fx;
    float p2n = __int_as_float((n + 127) << 23);
    return fmaxf(__fmul_rn(y, p2n), xin);
}

// XLA:CPU inline logf (Cephes, GenerateVF32Log). DO NOT TOUCH.
__device__ __forceinline__ float xla_logf(float xin)
{
    float x = fmaxf(xin, 1.17549435e-38f);
    int ix   = __float_as_int(x);
    int emm0 = (int)((unsigned int)ix >> 23) - 0x7e;
    float e  = (float)emm0;
    x = __int_as_float((ix & ~0x7f800000) | 0x3f000000);
    bool m = x < 0.707106781186547524f;
    float tmp = m ? x : 0.0f;
    x = __fsub_rn(x, 1.0f);
    e = __fsub_rn(e, m ? 1.0f : 0.0f);
    x = __fadd_rn(x, tmp);
    float z = __fmul_rn(x, x);
    float y = fmaf(7.0376836292E-2f, x, -1.1514610310E-1f);
    y = fmaf(y, x,  1.1676998740E-1f);
    y = fmaf(y, x, -1.2420140846E-1f);
    y = fmaf(y, x,  1.4249322787E-1f);
    y = fmaf(y, x, -1.6668057665E-1f);
    y = fmaf(y, x,  2.0000714765E-1f);
    y = fmaf(y, x, -2.4999993993E-1f);
    y = fmaf(y, x,  3.3333331174E-1f);
    y = __fmul_rn(y, x);
    y = __fmul_rn(y, z);
    y = fmaf(e, -2.12194440e-4f, y);
    y = fmaf(z, -0.5f, y);
    x = __fadd_rn(x, y);
    x = fmaf(e, 0.693359375f, x);
    return x;
}

__device__ __forceinline__ float cost_class_f(float x)
{
    float e   = xla_expf(-x);
    float p   = __fdiv_rn(1.0f, __fadd_rn(1.0f, e));
    float omp = __fsub_rn(1.0f, p);
    float lo  = xla_logf(__fadd_rn(omp, 1e-8f));
    float lp  = xla_logf(__fadd_rn(p,   1e-8f));
    float pp  = __fmul_rn(p,   p);
    float oo  = __fmul_rn(omp, omp);
    float neg = __fmul_rn(__fmul_rn(0.75f, pp), -lo);
    float pos = __fmul_rn(__fmul_rn(0.25f, oo), -lp);
    return __fsub_rn(pos, neg);
}

__device__ __forceinline__ float cost_entry_f(float cls, float px, float py,
                                              float gx, float gy)
{
    float coord = __fadd_rn(fabsf(__fsub_rn(px, gx)), fabsf(__fsub_rn(py, gy)));
    return __fadd_rn(cls, coord);
}

__device__ __forceinline__ unsigned f32_sortable(float x)
{
    int i = __float_as_int(x);
    return (i >= 0) ? ((unsigned)i ^ 0x80000000u) : ~(unsigned)i;
}

// ---------------------------------------------------------------------------
// Kernel 1: C matrix + pred_idx outputs. grid=(NN,BB), block=NN. (unchanged)
// ---------------------------------------------------------------------------
__global__ void cost_kernel(const float* __restrict__ logits,
                            const float2* __restrict__ pred_pts,
                            const float2* __restrict__ gt_pts,
                            float* __restrict__ pred_out,
                            float* __restrict__ Cf)
{
    const int i = blockIdx.x;
    const int b = blockIdx.y;
    const int j = threadIdx.x;

    __shared__ float s_cls, s_px, s_py;
    if (j == 0) {
        s_cls = cost_class_f(logits[b * NN + i]);
        float2 pp = pred_pts[b * NN + i];
        s_px = pp.x; s_py = pp.y;
        pred_out[b * NN + i] = (float)i;
    }
    __syncthreads();

    float2 gp = gt_pts[b * NN + j];
    Cf[((size_t)b * NN + i) * NN + j] = cost_entry_f(s_cls, s_px, s_py, gp.x, gp.y);
}

// ---------------------------------------------------------------------------
// Kernel 2: reference-buggy LSA. 128 threads/batch, thread t owns cols
// 4t+1..4t+4. f32 prefilter (conservative error radius) selects the tiny
// subset of candidates that could be the exact f64 argmin; only those pay
// FP64. Single barrier per step (parity-buffered reduction slots; u[] reads
// in prefetch are disjoint from all concurrent u[] updates within a walk).
// ---------------------------------------------------------------------------
__global__ void __launch_bounds__(128, 1)
lsa_kernel(const float* __restrict__ logits,
           const float2* __restrict__ pred_pts,
           const float2* __restrict__ gt_pts,
           float* __restrict__ gt_out)
{
    const int b    = blockIdx.x;
    const int t    = threadIdx.x;
    const int lane = t & 31;
    const int w    = t >> 5;
    const int c0   = 4 * t + 1;            // first owned column (1-indexed)

    __shared__ float  s_cls[NN], s_px[NN], s_py[NN];
    __shared__ double u[NN + 1];
    __shared__ int    p[NN + 1];
    __shared__ unsigned long long red_key[2][4];
    __shared__ int    red_col[2][4];

    for (int r = t; r < NN; r += 128) {
        s_cls[r] = cost_class_f(logits[b * NN + r]);
        float2 pp = pred_pts[b * NN + r];
        s_px[r] = pp.x; s_py[r] = pp.y;
    }
    float gx[4], gy[4];
    #pragma unroll
    for (int k = 0; k < 4; k++) {
        float2 g = gt_pts[b * NN + 4 * t + k];
        gx[k] = g.x; gy[k] = g.y;
    }
    #pragma unroll
    for (int k = 0; k < 4; k++) { u[c0 + k] = 0.0; p[c0 + k] = 0; }
    double v64[4] = {0.0, 0.0, 0.0, 0.0};
    float  v32[4] = {0.0f, 0.0f, 0.0f, 0.0f};
    __syncthreads();

    for (int i = 1; i <= NN; ++i) {
        unsigned usedMask = 0;
        int j0  = 0;
        int par = 0;

        // step-0 state: i0 = i, u[i] == 0 (row i never matched/active before)
        double ui0  = 0.0;
        float  ui0f = 0.0f;
        float  cf[4];
        {
            const float cls0 = s_cls[i - 1], px0 = s_px[i - 1], py0 = s_py[i - 1];
            #pragma unroll
            for (int k = 0; k < 4; k++)
                cf[k] = cost_entry_f(cls0, px0, py0, gx[k], gy[k]);
        }
        __syncthreads();   // row top: prev-row p/u writes visible

        for (;;) {
            // mark used[j0] (reference loop-top semantics)
            unsigned d = (unsigned)j0 - (unsigned)c0;
            if (d < 4u) usedMask |= 1u << d;

            // ---- f32 estimate + conservative radius; warp-min of (cc+err)
            float    cc[4], er[4];
            unsigned locUp = 0xffffffffu;
            #pragma unroll
            for (int k = 0; k < 4; k++) {
                float a = __fsub_rn(cf[k], ui0f);
                float c = __fsub_rn(a, v32[k]);
                // true |cc - cand64| <= 2^-24*(|a|+|u32|+|cc|+|v32|); use 2^-21 (8x slack)
                float e = (fabsf(c) + fabsf(a) + fabsf(ui0f) + fabsf(v32[k]))
                          * 4.76837158e-7f + 1e-35f;
                cc[k] = c; er[k] = e;
                if (!((usedMask >> k) & 1u)) {
                    unsigned su = f32_sortable(c + e);
                    locUp = (su < locUp) ? su : locUp;
                }
            }
            unsigned wUp = __reduce_min_sync(0xffffffffu, locUp);

            // ---- exact f64 only for lanes that can win this warp
            unsigned long long bk = ~0ull; int bc = 0;
            #pragma unroll
            for (int k = 0; k < 4; k++) {
                bool sub = !((usedMask >> k) & 1u) &&
                           (f32_sortable(cc[k] - er[k]) <= wUp);
                if (sub) {
                    double cd = ((double)cf[k] - ui0) - v64[k];   // exact ref order
                    long long bits = __double_as_longlong(cd);
                    unsigned long long kk = (bits >= 0)
                        ? ((unsigned long long)bits ^ SIGN64)
                        : ~(unsigned long long)bits;
                    if (kk < bk) { bk = kk; bc = c0 + k; }        // lowest col on tie
                }
            }

            // ---- warp u64 min via two u32 redux (exact), winner col by ballot
            unsigned hi  = (unsigned)(bk >> 32);
            unsigned mhi = __reduce_min_sync(0xffffffffu, hi);
            unsigned lo2 = (hi == mhi) ? (unsigned)bk : 0xffffffffu;
            unsigned mlo = __reduce_min_sync(0xffffffffu, lo2);
            unsigned long long mk = ((unsigned long long)mhi << 32) | mlo;
            unsigned ball = __ballot_sync(0xffffffffu, bk == mk);
            int src  = __ffs(ball) - 1;
            int wcol = __shfl_sync(0xffffffffu, bc, src);
            if (lane == 0) { red_key[par][w] = mk; red_col[par][w] = wcol; }
            __syncthreads();   // the ONLY barrier per step

            // ---- stage 2: 4 partials, serial (lower warp = lower cols on ties)
            unsigned long long bk2 = red_key[par][0]; int j1 = red_col[par][0];
            #pragma unroll
            for (int w2 = 1; w2 < 4; w2++) {
                unsigned long long kk = red_key[par][w2];
                if (kk < bk2) { bk2 = kk; j1 = red_col[par][w2]; }
            }
            long long db = (long long)((bk2 & SIGN64) ? (bk2 ^ SIGN64) : ~bk2);
            const double delta = __longlong_as_double(db);

            // ---- prefetch next step (u[p[j1]] untouched during this walk)
            const int  i0n = p[j1];
            const bool brk = (i0n == 0);
            if (!brk) {
                ui0  = u[i0n];
                ui0f = (float)ui0;
                const float cls0 = s_cls[i0n - 1], px0 = s_px[i0n - 1], py0 = s_py[i0n - 1];
                #pragma unroll
                for (int k = 0; k < 4; k++)
                    cf[k] = cost_entry_f(cls0, px0, py0, gx[k], gy[k]);
            }

            // ---- reference updates (sequential f64 rounding preserved)
            #pragma unroll
            for (int k = 0; k < 4; k++)
                if ((usedMask >> k) & 1u) {
                    u[p[c0 + k]] += delta;
                    v64[k] -= delta;
                    v32[k]  = (float)v64[k];
                }
            if (t == 0) u[i] += delta;      // index 0: p[0] = i

            j0 = j1;
            par ^= 1;
            if (brk) break;                 // next row-top barrier covers visibility
        }

        if (t == 0) p[j0] = i;              // way[] all zero -> single write
    }
    __syncthreads();

    #pragma unroll
    for (int k = 0; k < 4; k++)
        gt_out[b * NN + (p[c0 + k] - 1)] = (float)(c0 + k - 1);
}

// ---------------------------------------------------------------------------
// out = [pred_idx (B*N) | gt_idx (B*N) | C (B*N*N)], float32
// ---------------------------------------------------------------------------
extern "C" void kernel_launch(void* const* d_in, const int* in_sizes, int n_in,
                              void* d_out, int out_size)
{
    const float*  logits   = (const float*) d_in[0];
    const float2* pred_pts = (const float2*)d_in[1];
    const float2* gt_pts   = (const float2*)d_in[2];
    // d_in[3] = gt_mask (all true, unused)

    float* out  = (float*)d_out;
    float* pred = out;
    float* gt   = out + BB * NN;
    float* Cf   = out + 2 * BB * NN;

    dim3 cgrid(NN, BB);
    cost_kernel<<<cgrid, NN>>>(logits, pred_pts, gt_pts, pred, Cf);
    lsa_kernel<<<BB, 128>>>(logits, pred_pts, gt_pts, gt);
}